// round 5
// baseline (speedup 1.0000x reference)
#include <cuda_runtime.h>
#include <cuda_bf16.h>
#include <math_constants.h>

// Problem dims (fixed)
#define BB 2
#define SS 2048
#define DD 768
#define HH 12
#define DH 64
#define BH (BB*HH)          // 24
#define ROWS_TOTAL (BB*HH*SS) // 49152

// Scratch (device globals: sanctioned scratch mechanism)
__device__ float g_q[BB*HH*SS*DH];
__device__ float g_k[BB*HH*SS*DH];
__device__ float g_v[BB*HH*SS*DH];
__device__ float g_m[ROWS_TOTAL];
__device__ float g_l[ROWS_TOTAL];

// ---------------------------------------------------------------------------
// K1: QKV projection.  out[b,h,s,d] = sum_k hid[b,s,k]*W[n,k] + bias[n]
// NT GEMM  M=4096 (b*s), N=768 (h*d), K=768.  blockIdx.z selects q/k/v.
// ---------------------------------------------------------------------------
__global__ __launch_bounds__(256) void qkv_kernel(
    const float* __restrict__ hid,
    const float* __restrict__ Wq, const float* __restrict__ bq,
    const float* __restrict__ Wk, const float* __restrict__ bk,
    const float* __restrict__ Wv, const float* __restrict__ bv)
{
    const float* W; const float* bias; float* out;
    if (blockIdx.z == 0)      { W = Wq; bias = bq; out = g_q; }
    else if (blockIdx.z == 1) { W = Wk; bias = bk; out = g_k; }
    else                      { W = Wv; bias = bv; out = g_v; }

    __shared__ float As[16][128+4];
    __shared__ float Bs[16][128+4];

    const int tid = threadIdx.x;
    const int m0 = blockIdx.y * 128;
    const int n0 = blockIdx.x * 128;

    const int lr = tid >> 2;          // 0..63
    const int lc = (tid & 3) << 2;    // 0,4,8,12
    const int ty = tid >> 4;          // 0..15
    const int tx = tid & 15;          // 0..15

    float acc[8][8];
#pragma unroll
    for (int i = 0; i < 8; i++)
#pragma unroll
        for (int j = 0; j < 8; j++) acc[i][j] = 0.f;

    for (int k0 = 0; k0 < DD; k0 += 16) {
#pragma unroll
        for (int r = 0; r < 2; r++) {
            int row = lr + r*64;
            float4 a = *(const float4*)(hid + (size_t)(m0+row)*DD + k0 + lc);
            As[lc+0][row]=a.x; As[lc+1][row]=a.y; As[lc+2][row]=a.z; As[lc+3][row]=a.w;
            float4 w = *(const float4*)(W + (size_t)(n0+row)*DD + k0 + lc);
            Bs[lc+0][row]=w.x; Bs[lc+1][row]=w.y; Bs[lc+2][row]=w.z; Bs[lc+3][row]=w.w;
        }
        __syncthreads();
#pragma unroll
        for (int k = 0; k < 16; k++) {
            float ra[8], rb[8];
#pragma unroll
            for (int i = 0; i < 8; i++) ra[i] = As[k][ty*8+i];
#pragma unroll
            for (int j = 0; j < 8; j++) rb[j] = Bs[k][tx*8+j];
#pragma unroll
            for (int i = 0; i < 8; i++)
#pragma unroll
                for (int j = 0; j < 8; j++)
                    acc[i][j] += ra[i]*rb[j];
        }
        __syncthreads();
    }

#pragma unroll
    for (int i = 0; i < 8; i++) {
        int m = m0 + ty*8 + i;
        int b = m >> 11, s = m & 2047;
#pragma unroll
        for (int j = 0; j < 8; j++) {
            int n = n0 + tx*8 + j;
            int h = n >> 6, d = n & 63;
            out[(((size_t)(b*HH + h)*SS + s) << 6) + d] = acc[i][j] + bias[n];
        }
    }
}

// ---------------------------------------------------------------------------
// K2: scores = Q K^T * scale + res  -> written directly to scores_res_out
// per (b,h): M=N=2048, K=64.
// ---------------------------------------------------------------------------
__global__ __launch_bounds__(256) void scores_kernel(
    const float* __restrict__ res, float* __restrict__ out_scores)
{
    const int bh = blockIdx.z;
    const float* Q = g_q + (size_t)bh * SS * DH;
    const float* Kp = g_k + (size_t)bh * SS * DH;
    const float* R = res + (size_t)bh * SS * SS;
    float* O = out_scores + (size_t)bh * SS * SS;

    __shared__ float As[16][128+4];
    __shared__ float Bs[16][128+4];

    const int tid = threadIdx.x;
    const int m0 = blockIdx.y * 128;
    const int n0 = blockIdx.x * 128;
    const int lr = tid >> 2;
    const int lc = (tid & 3) << 2;
    const int ty = tid >> 4;
    const int tx = tid & 15;

    float acc[8][8];
#pragma unroll
    for (int i = 0; i < 8; i++)
#pragma unroll
        for (int j = 0; j < 8; j++) acc[i][j] = 0.f;

#pragma unroll
    for (int k0 = 0; k0 < DH; k0 += 16) {
#pragma unroll
        for (int r = 0; r < 2; r++) {
            int row = lr + r*64;
            float4 a = *(const float4*)(Q + (size_t)(m0+row)*DH + k0 + lc);
            As[lc+0][row]=a.x; As[lc+1][row]=a.y; As[lc+2][row]=a.z; As[lc+3][row]=a.w;
            float4 kk = *(const float4*)(Kp + (size_t)(n0+row)*DH + k0 + lc);
            Bs[lc+0][row]=kk.x; Bs[lc+1][row]=kk.y; Bs[lc+2][row]=kk.z; Bs[lc+3][row]=kk.w;
        }
        __syncthreads();
#pragma unroll
        for (int k = 0; k < 16; k++) {
            float ra[8], rb[8];
#pragma unroll
            for (int i = 0; i < 8; i++) ra[i] = As[k][ty*8+i];
#pragma unroll
            for (int j = 0; j < 8; j++) rb[j] = Bs[k][tx*8+j];
#pragma unroll
            for (int i = 0; i < 8; i++)
#pragma unroll
                for (int j = 0; j < 8; j++)
                    acc[i][j] += ra[i]*rb[j];
        }
        __syncthreads();
    }

    const float scale = 0.125f; // 1/sqrt(64)
#pragma unroll
    for (int i = 0; i < 8; i++) {
        int m = m0 + ty*8 + i;
        size_t base = (size_t)m*SS + n0 + tx*8;
#pragma unroll
        for (int j2 = 0; j2 < 2; j2++) {
            float4 r = *(const float4*)(R + base + j2*4);
            float4 o;
            o.x = acc[i][j2*4+0]*scale + r.x;
            o.y = acc[i][j2*4+1]*scale + r.y;
            o.z = acc[i][j2*4+2]*scale + r.z;
            o.w = acc[i][j2*4+3]*scale + r.w;
            *(float4*)(O + base + j2*4) = o;
        }
    }
}

// ---------------------------------------------------------------------------
// K3: per-row softmax stats over (scores + mask): rowmax m, sum l
// 4 rows per block (one per 2 warps? -> simple: loop 4 rows per block).
// ---------------------------------------------------------------------------
__device__ __forceinline__ float warpRedMax(float v) {
#pragma unroll
    for (int o = 16; o > 0; o >>= 1) v = fmaxf(v, __shfl_xor_sync(0xffffffffu, v, o));
    return v;
}
__device__ __forceinline__ float warpRedSum(float v) {
#pragma unroll
    for (int o = 16; o > 0; o >>= 1) v += __shfl_xor_sync(0xffffffffu, v, o);
    return v;
}

__global__ __launch_bounds__(256) void softmax_stats_kernel(
    const float* __restrict__ scores, const float* __restrict__ mask)
{
    const int tid = threadIdx.x;
    __shared__ float red[8];

#pragma unroll
    for (int rr = 0; rr < 4; rr++) {
        const int row = blockIdx.x * 4 + rr;         // 0..49151
        const int b = row / (HH*SS);
        const float* sr = scores + (size_t)row * SS;
        const float* mr = mask + (size_t)b * SS;

        float vals[8];
        float lm = -CUDART_INF_F;
#pragma unroll
        for (int i = 0; i < 8; i++) {
            int c = tid + i*256;
            float v = sr[c] + mr[c];
            vals[i] = v;
            lm = fmaxf(lm, v);
        }

        float wm = warpRedMax(lm);
        if ((tid & 31) == 0) red[tid >> 5] = wm;
        __syncthreads();
        float bm = red[0];
#pragma unroll
        for (int w = 1; w < 8; w++) bm = fmaxf(bm, red[w]);

        float ls = 0.f;
#pragma unroll
        for (int i = 0; i < 8; i++) ls += __expf(vals[i] - bm);
        __syncthreads();
        float ws = warpRedSum(ls);
        if ((tid & 31) == 0) red[tid >> 5] = ws;
        __syncthreads();
        if (tid == 0) {
            float s = 0.f;
#pragma unroll
            for (int w = 0; w < 8; w++) s += red[w];
            g_m[row] = bm;
            g_l[row] = s;
        }
        __syncthreads();
    }
}

// ---------------------------------------------------------------------------
// K4: ctx = softmax(scores+mask) @ V, probs computed on the fly.
// per (b,h): M=2048, N=64, K=2048.  Tile 128x64, BK=32, thread tile 8x4.
// 1/l normalization folded into the epilogue (linear in P).
// ---------------------------------------------------------------------------
__global__ __launch_bounds__(256) void pv_kernel(
    const float* __restrict__ scores, const float* __restrict__ mask,
    float* __restrict__ ctx)
{
    const int bh = blockIdx.z;
    const int b = bh / HH, h = bh % HH;
    const float* P = scores + (size_t)bh * SS * SS;
    const float* V = g_v + (size_t)bh * SS * DH;
    const float* mr = mask + (size_t)b * SS;
    const int m0 = blockIdx.y * 128;
    const int tid = threadIdx.x;

    __shared__ float Ps[32][128+4];
    __shared__ float Vs[32][64+4];
    __shared__ float ms[128], rls[128];

    if (tid < 128) {
        int r = bh*SS + m0 + tid;
        ms[tid]  = g_m[r];
        rls[tid] = 1.0f / g_l[r];
    }
    __syncthreads();

    const int ty = tid >> 4;   // 0..15 -> 8 rows each
    const int tx = tid & 15;   // 0..15 -> 4 cols each
    const int pr  = tid >> 1;          // 0..127 (P tile row)
    const int pc0 = (tid & 1) * 16;    // 0 or 16

    float acc[8][4];
#pragma unroll
    for (int i = 0; i < 8; i++)
#pragma unroll
        for (int j = 0; j < 4; j++) acc[i][j] = 0.f;

    const float mrow = ms[pr];
    const float* prow = P + (size_t)(m0 + pr) * SS;

    for (int k0 = 0; k0 < SS; k0 += 32) {
        // P tile: exp((s+mask)-m), stored transposed [k][m]
#pragma unroll
        for (int i = 0; i < 4; i++) {
            int c = pc0 + i*4;
            float4 v = *(const float4*)(prow + k0 + c);
            float4 mk = *(const float4*)(mr + k0 + c);
            Ps[c+0][pr] = __expf(v.x + mk.x - mrow);
            Ps[c+1][pr] = __expf(v.y + mk.y - mrow);
            Ps[c+2][pr] = __expf(v.z + mk.z - mrow);
            Ps[c+3][pr] = __expf(v.w + mk.w - mrow);
        }
        // V tile [32][64]
#pragma unroll
        for (int r = 0; r < 2; r++) {
            int vr = (tid >> 4) + r*16;
            int vc = (tid & 15) * 4;
            float4 v4 = *(const float4*)(V + (size_t)(k0+vr)*DH + vc);
            *(float4*)&Vs[vr][vc] = v4;
        }
        __syncthreads();
#pragma unroll
        for (int k = 0; k < 32; k++) {
            float ra[8], rb[4];
#pragma unroll
            for (int i = 0; i < 8; i++) ra[i] = Ps[k][ty*8+i];
#pragma unroll
            for (int j = 0; j < 4; j++) rb[j] = Vs[k][tx*4+j];
#pragma unroll
            for (int i = 0; i < 8; i++)
#pragma unroll
                for (int j = 0; j < 4; j++)
                    acc[i][j] += ra[i]*rb[j];
        }
        __syncthreads();
    }

#pragma unroll
    for (int i = 0; i < 8; i++) {
        int m = m0 + ty*8 + i;
        float rl = rls[ty*8+i];
        float4 o = make_float4(acc[i][0]*rl, acc[i][1]*rl, acc[i][2]*rl, acc[i][3]*rl);
        *(float4*)(ctx + ((size_t)b*SS + m)*DD + h*DH + tx*4) = o;
    }
}

// ---------------------------------------------------------------------------
extern "C" void kernel_launch(void* const* d_in, const int* in_sizes, int n_in,
                              void* d_out, int out_size)
{
    const float* hid  = (const float*)d_in[0];
    const float* mask = (const float*)d_in[1];
    const float* res  = (const float*)d_in[2];
    const float* Wq = (const float*)d_in[3];
    const float* bq = (const float*)d_in[4];
    const float* Wk = (const float*)d_in[5];
    const float* bk = (const float*)d_in[6];
    const float* Wv = (const float*)d_in[7];
    const float* bv = (const float*)d_in[8];

    float* out_ctx    = (float*)d_out;
    float* out_scores = (float*)d_out + (size_t)BB*SS*DD;

    qkv_kernel<<<dim3(DD/128, (BB*SS)/128, 3), 256>>>(hid, Wq, bq, Wk, bk, Wv, bv);
    scores_kernel<<<dim3(SS/128, SS/128, BH), 256>>>(res, out_scores);
    softmax_stats_kernel<<<dim3(ROWS_TOTAL/4), 256>>>(out_scores, mask);
    pv_kernel<<<dim3(1, SS/128, BH), 256>>>(out_scores, mask, out_ctx);
}

// round 6
// speedup vs baseline: 1.0777x; 1.0777x over previous
#include <cuda_runtime.h>
#include <cuda_bf16.h>
#include <math_constants.h>

// Problem dims (fixed)
#define BB 2
#define SS 2048
#define DD 768
#define HH 12
#define DH 64
#define BH (BB*HH)          // 24
#define ROWS_TOTAL (BB*HH*SS) // 49152

typedef unsigned long long u64;

// ---- packed f32x2 helpers (Blackwell FFMA2 path) --------------------------
__device__ __forceinline__ u64 dup2(float v) {
    u64 r; asm("mov.b64 %0, {%1, %1};" : "=l"(r) : "f"(v)); return r;
}
__device__ __forceinline__ void fma2(u64& d, u64 a, u64 b) {
    asm("fma.rn.f32x2 %0, %1, %2, %0;" : "+l"(d) : "l"(a), "l"(b));
}
__device__ __forceinline__ float2 unpack2(u64 v) {
    float2 r; asm("mov.b64 {%0, %1}, %2;" : "=f"(r.x), "=f"(r.y) : "l"(v)); return r;
}

// Scratch (device globals: sanctioned scratch mechanism)
__device__ float g_q[BB*HH*SS*DH];
__device__ float g_k[BB*HH*SS*DH];
__device__ float g_v[BB*HH*SS*DH];
__device__ float g_m[ROWS_TOTAL];
__device__ float g_l[ROWS_TOTAL];

// ---------------------------------------------------------------------------
// K1: QKV projection.  out[b,h,s,d] = sum_k hid[b,s,k]*W[n,k] + bias[n]
// NT GEMM  M=4096 (b*s), N=768 (h*d), K=768.  blockIdx.z selects q/k/v.
// Inner loop: packed f32x2 FMAs, pairs along j (n), dup along i (m).
// ---------------------------------------------------------------------------
__global__ __launch_bounds__(256) void qkv_kernel(
    const float* __restrict__ hid,
    const float* __restrict__ Wq, const float* __restrict__ bq,
    const float* __restrict__ Wk, const float* __restrict__ bk,
    const float* __restrict__ Wv, const float* __restrict__ bv)
{
    const float* W; const float* bias; float* out;
    if (blockIdx.z == 0)      { W = Wq; bias = bq; out = g_q; }
    else if (blockIdx.z == 1) { W = Wk; bias = bk; out = g_k; }
    else                      { W = Wv; bias = bv; out = g_v; }

    __shared__ __align__(16) float As[16][128+4];
    __shared__ __align__(16) float Bs[16][128+4];

    const int tid = threadIdx.x;
    const int m0 = blockIdx.y * 128;
    const int n0 = blockIdx.x * 128;

    const int lr = tid >> 2;          // 0..63
    const int lc = (tid & 3) << 2;    // 0,4,8,12
    const int ty = tid >> 4;          // 0..15
    const int tx = tid & 15;          // 0..15

    u64 acc2[8][4];                   // [i][j-pair]
#pragma unroll
    for (int i = 0; i < 8; i++)
#pragma unroll
        for (int j = 0; j < 4; j++) acc2[i][j] = 0ull;

    for (int k0 = 0; k0 < DD; k0 += 16) {
#pragma unroll
        for (int r = 0; r < 2; r++) {
            int row = lr + r*64;
            float4 a = *(const float4*)(hid + (size_t)(m0+row)*DD + k0 + lc);
            As[lc+0][row]=a.x; As[lc+1][row]=a.y; As[lc+2][row]=a.z; As[lc+3][row]=a.w;
            float4 w = *(const float4*)(W + (size_t)(n0+row)*DD + k0 + lc);
            Bs[lc+0][row]=w.x; Bs[lc+1][row]=w.y; Bs[lc+2][row]=w.z; Bs[lc+3][row]=w.w;
        }
        __syncthreads();
#pragma unroll
        for (int k = 0; k < 16; k++) {
            float4 a0 = *(const float4*)&As[k][ty*8];
            float4 a1 = *(const float4*)&As[k][ty*8+4];
            u64 ra2[8];
            ra2[0]=dup2(a0.x); ra2[1]=dup2(a0.y); ra2[2]=dup2(a0.z); ra2[3]=dup2(a0.w);
            ra2[4]=dup2(a1.x); ra2[5]=dup2(a1.y); ra2[6]=dup2(a1.z); ra2[7]=dup2(a1.w);
            ulonglong2 b0 = *(const ulonglong2*)&Bs[k][tx*8];
            ulonglong2 b1 = *(const ulonglong2*)&Bs[k][tx*8+4];
            u64 rb2[4] = { b0.x, b0.y, b1.x, b1.y };
#pragma unroll
            for (int i = 0; i < 8; i++)
#pragma unroll
                for (int j = 0; j < 4; j++)
                    fma2(acc2[i][j], ra2[i], rb2[j]);
        }
        __syncthreads();
    }

#pragma unroll
    for (int i = 0; i < 8; i++) {
        int m = m0 + ty*8 + i;
        int b = m >> 11, s = m & 2047;
#pragma unroll
        for (int j2 = 0; j2 < 4; j2++) {
            float2 p = unpack2(acc2[i][j2]);
            int n = n0 + tx*8 + j2*2;
            int h0 = n >> 6, d0 = n & 63;
            int h1 = (n+1) >> 6, d1 = (n+1) & 63;
            out[(((size_t)(b*HH + h0)*SS + s) << 6) + d0] = p.x + bias[n];
            out[(((size_t)(b*HH + h1)*SS + s) << 6) + d1] = p.y + bias[n+1];
        }
    }
}

// ---------------------------------------------------------------------------
// K2: scores = Q K^T * scale + res  -> written directly to scores_res_out
// per (b,h): M=N=2048, K=64.  Packed f32x2 inner loop.
// ---------------------------------------------------------------------------
__global__ __launch_bounds__(256) void scores_kernel(
    const float* __restrict__ res, float* __restrict__ out_scores)
{
    const int bh = blockIdx.z;
    const float* Q = g_q + (size_t)bh * SS * DH;
    const float* Kp = g_k + (size_t)bh * SS * DH;
    const float* R = res + (size_t)bh * SS * SS;
    float* O = out_scores + (size_t)bh * SS * SS;

    __shared__ __align__(16) float As[16][128+4];
    __shared__ __align__(16) float Bs[16][128+4];

    const int tid = threadIdx.x;
    const int m0 = blockIdx.y * 128;
    const int n0 = blockIdx.x * 128;
    const int lr = tid >> 2;
    const int lc = (tid & 3) << 2;
    const int ty = tid >> 4;
    const int tx = tid & 15;

    u64 acc2[8][4];
#pragma unroll
    for (int i = 0; i < 8; i++)
#pragma unroll
        for (int j = 0; j < 4; j++) acc2[i][j] = 0ull;

#pragma unroll
    for (int k0 = 0; k0 < DH; k0 += 16) {
#pragma unroll
        for (int r = 0; r < 2; r++) {
            int row = lr + r*64;
            float4 a = *(const float4*)(Q + (size_t)(m0+row)*DH + k0 + lc);
            As[lc+0][row]=a.x; As[lc+1][row]=a.y; As[lc+2][row]=a.z; As[lc+3][row]=a.w;
            float4 kk = *(const float4*)(Kp + (size_t)(n0+row)*DH + k0 + lc);
            Bs[lc+0][row]=kk.x; Bs[lc+1][row]=kk.y; Bs[lc+2][row]=kk.z; Bs[lc+3][row]=kk.w;
        }
        __syncthreads();
#pragma unroll
        for (int k = 0; k < 16; k++) {
            float4 a0 = *(const float4*)&As[k][ty*8];
            float4 a1 = *(const float4*)&As[k][ty*8+4];
            u64 ra2[8];
            ra2[0]=dup2(a0.x); ra2[1]=dup2(a0.y); ra2[2]=dup2(a0.z); ra2[3]=dup2(a0.w);
            ra2[4]=dup2(a1.x); ra2[5]=dup2(a1.y); ra2[6]=dup2(a1.z); ra2[7]=dup2(a1.w);
            ulonglong2 b0 = *(const ulonglong2*)&Bs[k][tx*8];
            ulonglong2 b1 = *(const ulonglong2*)&Bs[k][tx*8+4];
            u64 rb2[4] = { b0.x, b0.y, b1.x, b1.y };
#pragma unroll
            for (int i = 0; i < 8; i++)
#pragma unroll
                for (int j = 0; j < 4; j++)
                    fma2(acc2[i][j], ra2[i], rb2[j]);
        }
        __syncthreads();
    }

    const float scale = 0.125f; // 1/sqrt(64)
#pragma unroll
    for (int i = 0; i < 8; i++) {
        int m = m0 + ty*8 + i;
        size_t base = (size_t)m*SS + n0 + tx*8;
#pragma unroll
        for (int h = 0; h < 2; h++) {
            float2 p0 = unpack2(acc2[i][h*2+0]);
            float2 p1 = unpack2(acc2[i][h*2+1]);
            float4 r = *(const float4*)(R + base + h*4);
            float4 o;
            o.x = p0.x*scale + r.x;
            o.y = p0.y*scale + r.y;
            o.z = p1.x*scale + r.z;
            o.w = p1.y*scale + r.w;
            *(float4*)(O + base + h*4) = o;
        }
    }
}

// ---------------------------------------------------------------------------
// K3: per-row softmax stats over (scores + mask): rowmax m, sum l
// ---------------------------------------------------------------------------
__device__ __forceinline__ float warpRedMax(float v) {
#pragma unroll
    for (int o = 16; o > 0; o >>= 1) v = fmaxf(v, __shfl_xor_sync(0xffffffffu, v, o));
    return v;
}
__device__ __forceinline__ float warpRedSum(float v) {
#pragma unroll
    for (int o = 16; o > 0; o >>= 1) v += __shfl_xor_sync(0xffffffffu, v, o);
    return v;
}

__global__ __launch_bounds__(256) void softmax_stats_kernel(
    const float* __restrict__ scores, const float* __restrict__ mask)
{
    const int tid = threadIdx.x;
    __shared__ float red[8];

#pragma unroll
    for (int rr = 0; rr < 4; rr++) {
        const int row = blockIdx.x * 4 + rr;         // 0..49151
        const int b = row / (HH*SS);
        const float* sr = scores + (size_t)row * SS;
        const float* mr = mask + (size_t)b * SS;

        float vals[8];
        float lm = -CUDART_INF_F;
#pragma unroll
        for (int i = 0; i < 8; i++) {
            int c = tid + i*256;
            float v = sr[c] + mr[c];
            vals[i] = v;
            lm = fmaxf(lm, v);
        }

        float wm = warpRedMax(lm);
        if ((tid & 31) == 0) red[tid >> 5] = wm;
        __syncthreads();
        float bm = red[0];
#pragma unroll
        for (int w = 1; w < 8; w++) bm = fmaxf(bm, red[w]);

        float ls = 0.f;
#pragma unroll
        for (int i = 0; i < 8; i++) ls += __expf(vals[i] - bm);
        __syncthreads();
        float ws = warpRedSum(ls);
        if ((tid & 31) == 0) red[tid >> 5] = ws;
        __syncthreads();
        if (tid == 0) {
            float s = 0.f;
#pragma unroll
            for (int w = 0; w < 8; w++) s += red[w];
            g_m[row] = bm;
            g_l[row] = s;
        }
        __syncthreads();
    }
}

// ---------------------------------------------------------------------------
// K4: ctx = softmax(scores+mask) @ V, probs computed on the fly.
// per (b,h): M=2048, N=64, K=2048.  Tile 128x64, BK=32, thread tile 8x4.
// Packed f32x2: pairs along i (m, contiguous in transposed Ps), dup along j.
// 1/l folded into epilogue.
// ---------------------------------------------------------------------------
__global__ __launch_bounds__(256) void pv_kernel(
    const float* __restrict__ scores, const float* __restrict__ mask,
    float* __restrict__ ctx)
{
    const int bh = blockIdx.z;
    const int b = bh / HH, h = bh % HH;
    const float* P = scores + (size_t)bh * SS * SS;
    const float* V = g_v + (size_t)bh * SS * DH;
    const float* mr = mask + (size_t)b * SS;
    const int m0 = blockIdx.y * 128;
    const int tid = threadIdx.x;

    __shared__ __align__(16) float Ps[32][128+4];
    __shared__ __align__(16) float Vs[32][64+4];
    __shared__ float ms[128], rls[128];

    if (tid < 128) {
        int r = bh*SS + m0 + tid;
        ms[tid]  = g_m[r];
        rls[tid] = 1.0f / g_l[r];
    }
    __syncthreads();

    const int ty = tid >> 4;   // 0..15 -> 8 rows each
    const int tx = tid & 15;   // 0..15 -> 4 cols each
    const int pr  = tid >> 1;          // 0..127 (P tile row)
    const int pc0 = (tid & 1) * 16;    // 0 or 16

    u64 acc2[4][4];            // [i-pair][j]: pair = rows (2*i2, 2*i2+1)
#pragma unroll
    for (int i = 0; i < 4; i++)
#pragma unroll
        for (int j = 0; j < 4; j++) acc2[i][j] = 0ull;

    const float mrow = ms[pr];
    const float* prow = P + (size_t)(m0 + pr) * SS;

    for (int k0 = 0; k0 < SS; k0 += 32) {
        // P tile: exp((s+mask)-m), stored transposed [k][m]
#pragma unroll
        for (int i = 0; i < 4; i++) {
            int c = pc0 + i*4;
            float4 v = *(const float4*)(prow + k0 + c);
            float4 mk = *(const float4*)(mr + k0 + c);
            Ps[c+0][pr] = __expf(v.x + mk.x - mrow);
            Ps[c+1][pr] = __expf(v.y + mk.y - mrow);
            Ps[c+2][pr] = __expf(v.z + mk.z - mrow);
            Ps[c+3][pr] = __expf(v.w + mk.w - mrow);
        }
        // V tile [32][64]
#pragma unroll
        for (int r = 0; r < 2; r++) {
            int vr = (tid >> 4) + r*16;
            int vc = (tid & 15) * 4;
            float4 v4 = *(const float4*)(V + (size_t)(k0+vr)*DH + vc);
            *(float4*)&Vs[vr][vc] = v4;
        }
        __syncthreads();
#pragma unroll
        for (int k = 0; k < 32; k++) {
            ulonglong2 a0 = *(const ulonglong2*)&Ps[k][ty*8];
            ulonglong2 a1 = *(const ulonglong2*)&Ps[k][ty*8+4];
            u64 ra2[4] = { a0.x, a0.y, a1.x, a1.y };
            float4 bv4 = *(const float4*)&Vs[k][tx*4];
            u64 rb2[4] = { dup2(bv4.x), dup2(bv4.y), dup2(bv4.z), dup2(bv4.w) };
#pragma unroll
            for (int i = 0; i < 4; i++)
#pragma unroll
                for (int j = 0; j < 4; j++)
                    fma2(acc2[i][j], ra2[i], rb2[j]);
        }
        __syncthreads();
    }

    // unpack: acc2[i2][j] holds rows (2*i2, 2*i2+1), col j
#pragma unroll
    for (int i2 = 0; i2 < 4; i2++) {
        float2 c0 = unpack2(acc2[i2][0]);
        float2 c1 = unpack2(acc2[i2][1]);
        float2 c2 = unpack2(acc2[i2][2]);
        float2 c3 = unpack2(acc2[i2][3]);

        int iA = 2*i2, iB = 2*i2 + 1;
        int mA = m0 + ty*8 + iA;
        int mB = m0 + ty*8 + iB;
        float rlA = rls[ty*8+iA];
        float rlB = rls[ty*8+iB];
        float4 oA = make_float4(c0.x*rlA, c1.x*rlA, c2.x*rlA, c3.x*rlA);
        float4 oB = make_float4(c0.y*rlB, c1.y*rlB, c2.y*rlB, c3.y*rlB);
        *(float4*)(ctx + ((size_t)b*SS + mA)*DD + h*DH + tx*4) = oA;
        *(float4*)(ctx + ((size_t)b*SS + mB)*DD + h*DH + tx*4) = oB;
    }
}

// ---------------------------------------------------------------------------
extern "C" void kernel_launch(void* const* d_in, const int* in_sizes, int n_in,
                              void* d_out, int out_size)
{
    const float* hid  = (const float*)d_in[0];
    const float* mask = (const float*)d_in[1];
    const float* res  = (const float*)d_in[2];
    const float* Wq = (const float*)d_in[3];
    const float* bq = (const float*)d_in[4];
    const float* Wk = (const float*)d_in[5];
    const float* bk = (const float*)d_in[6];
    const float* Wv = (const float*)d_in[7];
    const float* bv = (const float*)d_in[8];

    float* out_ctx    = (float*)d_out;
    float* out_scores = (float*)d_out + (size_t)BB*SS*DD;

    qkv_kernel<<<dim3(DD/128, (BB*SS)/128, 3), 256>>>(hid, Wq, bq, Wk, bk, Wv, bv);
    scores_kernel<<<dim3(SS/128, SS/128, BH), 256>>>(res, out_scores);
    softmax_stats_kernel<<<dim3(ROWS_TOTAL/4), 256>>>(out_scores, mask);
    pv_kernel<<<dim3(1, SS/128, BH), 256>>>(out_scores, mask, out_ctx);
}

// round 8
// speedup vs baseline: 1.0952x; 1.0162x over previous
#include <cuda_runtime.h>
#include <cuda_bf16.h>
#include <math_constants.h>
#include <cstdint>

// Problem dims (fixed)
#define BB 2
#define SS 2048
#define DD 768
#define HH 12
#define DH 64
#define BH (BB*HH)          // 24
#define ROWS_TOTAL (BB*HH*SS) // 49152

typedef unsigned long long u64;

// ---- packed f32x2 helpers (Blackwell FFMA2 path) --------------------------
__device__ __forceinline__ u64 dup2(float v) {
    u64 r; asm("mov.b64 %0, {%1, %1};" : "=l"(r) : "f"(v)); return r;
}
__device__ __forceinline__ void fma2(u64& d, u64 a, u64 b) {
    asm("fma.rn.f32x2 %0, %1, %2, %0;" : "+l"(d) : "l"(a), "l"(b));
}
__device__ __forceinline__ float2 unpack2(u64 v) {
    float2 r; asm("mov.b64 {%0, %1}, %2;" : "=f"(r.x), "=f"(r.y) : "l"(v)); return r;
}

// Scratch (device globals: sanctioned scratch mechanism)
__device__ __nv_bfloat16 g_qh[BB*HH*SS*DH];  // Q*0.125 split-hi
__device__ __nv_bfloat16 g_ql[BB*HH*SS*DH];  // Q*0.125 split-lo
__device__ __nv_bfloat16 g_kh[BB*HH*SS*DH];
__device__ __nv_bfloat16 g_kl[BB*HH*SS*DH];
__device__ float g_v[BB*HH*SS*DH];
__device__ float g_m[ROWS_TOTAL];
__device__ float g_l[ROWS_TOTAL];

__device__ __forceinline__ uint32_t smem_u32(const void* p) {
    uint32_t a;
    asm("{ .reg .u64 t; cvta.to.shared.u64 t, %1; cvt.u32.u64 %0, t; }" : "=r"(a) : "l"(p));
    return a;
}
__device__ __forceinline__ void ldmx4(uint32_t* r, uint32_t addr) {
    asm volatile("ldmatrix.sync.aligned.m8n8.x4.shared.b16 {%0,%1,%2,%3}, [%4];"
        : "=r"(r[0]), "=r"(r[1]), "=r"(r[2]), "=r"(r[3]) : "r"(addr));
}
__device__ __forceinline__ void mma16816(float* c, const uint32_t* a, uint32_t b0, uint32_t b1) {
    asm volatile(
        "mma.sync.aligned.m16n8k16.row.col.f32.bf16.bf16.f32 "
        "{%0,%1,%2,%3},{%4,%5,%6,%7},{%8,%9},{%0,%1,%2,%3};"
        : "+f"(c[0]), "+f"(c[1]), "+f"(c[2]), "+f"(c[3])
        : "r"(a[0]), "r"(a[1]), "r"(a[2]), "r"(a[3]), "r"(b0), "r"(b1));
}

// ---------------------------------------------------------------------------
// K1: QKV projection. q,k written as bf16 hi/lo splits (q pre-scaled 0.125);
// v written fp32.
// ---------------------------------------------------------------------------
__global__ __launch_bounds__(256) void qkv_kernel(
    const float* __restrict__ hid,
    const float* __restrict__ Wq, const float* __restrict__ bq,
    const float* __restrict__ Wk, const float* __restrict__ bk,
    const float* __restrict__ Wv, const float* __restrict__ bv)
{
    const float* W; const float* bias;
    if (blockIdx.z == 0)      { W = Wq; bias = bq; }
    else if (blockIdx.z == 1) { W = Wk; bias = bk; }
    else                      { W = Wv; bias = bv; }

    __shared__ __align__(16) float As[16][128+4];
    __shared__ __align__(16) float Bs[16][128+4];

    const int tid = threadIdx.x;
    const int m0 = blockIdx.y * 128;
    const int n0 = blockIdx.x * 128;

    const int lr = tid >> 2;          // 0..63
    const int lc = (tid & 3) << 2;    // 0,4,8,12
    const int ty = tid >> 4;          // 0..15
    const int tx = tid & 15;          // 0..15

    u64 acc2[8][4];                   // [i][j-pair]
#pragma unroll
    for (int i = 0; i < 8; i++)
#pragma unroll
        for (int j = 0; j < 4; j++) acc2[i][j] = 0ull;

    for (int k0 = 0; k0 < DD; k0 += 16) {
#pragma unroll
        for (int r = 0; r < 2; r++) {
            int row = lr + r*64;
            float4 a = *(const float4*)(hid + (size_t)(m0+row)*DD + k0 + lc);
            As[lc+0][row]=a.x; As[lc+1][row]=a.y; As[lc+2][row]=a.z; As[lc+3][row]=a.w;
            float4 w = *(const float4*)(W + (size_t)(n0+row)*DD + k0 + lc);
            Bs[lc+0][row]=w.x; Bs[lc+1][row]=w.y; Bs[lc+2][row]=w.z; Bs[lc+3][row]=w.w;
        }
        __syncthreads();
#pragma unroll
        for (int k = 0; k < 16; k++) {
            float4 a0 = *(const float4*)&As[k][ty*8];
            float4 a1 = *(const float4*)&As[k][ty*8+4];
            u64 ra2[8];
            ra2[0]=dup2(a0.x); ra2[1]=dup2(a0.y); ra2[2]=dup2(a0.z); ra2[3]=dup2(a0.w);
            ra2[4]=dup2(a1.x); ra2[5]=dup2(a1.y); ra2[6]=dup2(a1.z); ra2[7]=dup2(a1.w);
            ulonglong2 b0 = *(const ulonglong2*)&Bs[k][tx*8];
            ulonglong2 b1 = *(const ulonglong2*)&Bs[k][tx*8+4];
            u64 rb2[4] = { b0.x, b0.y, b1.x, b1.y };
#pragma unroll
            for (int i = 0; i < 8; i++)
#pragma unroll
                for (int j = 0; j < 4; j++)
                    fma2(acc2[i][j], ra2[i], rb2[j]);
        }
        __syncthreads();
    }

    if (blockIdx.z == 2) {
#pragma unroll
        for (int i = 0; i < 8; i++) {
            int m = m0 + ty*8 + i;
            int b = m >> 11, s = m & 2047;
#pragma unroll
            for (int j2 = 0; j2 < 4; j2++) {
                float2 p = unpack2(acc2[i][j2]);
                int n = n0 + tx*8 + j2*2;
                int h0 = n >> 6, d0 = n & 63;
                int h1 = (n+1) >> 6, d1 = (n+1) & 63;
                g_v[(((size_t)(b*HH + h0)*SS + s) << 6) + d0] = p.x + bias[n];
                g_v[(((size_t)(b*HH + h1)*SS + s) << 6) + d1] = p.y + bias[n+1];
            }
        }
    } else {
        const float sc = (blockIdx.z == 0) ? 0.125f : 1.0f;
        __nv_bfloat16* oh = (blockIdx.z == 0) ? g_qh : g_kh;
        __nv_bfloat16* ol = (blockIdx.z == 0) ? g_ql : g_kl;
#pragma unroll
        for (int i = 0; i < 8; i++) {
            int m = m0 + ty*8 + i;
            int b = m >> 11, s = m & 2047;
#pragma unroll
            for (int j2 = 0; j2 < 4; j2++) {
                float2 p = unpack2(acc2[i][j2]);
                int n = n0 + tx*8 + j2*2;
#pragma unroll
                for (int e = 0; e < 2; e++) {
                    int ne = n + e;
                    float x = ((e == 0 ? p.x : p.y) + bias[ne]) * sc;
                    __nv_bfloat16 hi = __float2bfloat16(x);
                    __nv_bfloat16 lo = __float2bfloat16(x - __bfloat162float(hi));
                    int h = ne >> 6, d = ne & 63;
                    size_t idx = (((size_t)(b*HH + h)*SS + s) << 6) + d;
                    oh[idx] = hi;
                    ol[idx] = lo;
                }
            }
        }
    }
}

// ---------------------------------------------------------------------------
// K2 (mma.sync HMMA): scores = Qs K^T + res  (Q pre-scaled 1/8, bf16 3-split)
// Block tile 128x128, K=64. 8 warps as 4(m) x 2(n): warp tile 32x64.
// A = Q[m,k] row-major, B = K[n,k] (col-major for mma) — both ldmatrix, no trans.
// ---------------------------------------------------------------------------
#define SMM_SMEM (4*16384)

__global__ __launch_bounds__(256) void scores_mma_kernel(
    const float* __restrict__ res, float* __restrict__ out_scores)
{
    extern __shared__ __align__(1024) char smem[];
    const int OF_QH = 0, OF_QL = 16384, OF_KH = 32768, OF_KL = 49152;

    const int tid = threadIdx.x;
    const int bh = blockIdx.z;
    const int m0 = blockIdx.y * 128;
    const int n0 = blockIdx.x * 128;
    const uint32_t sb = smem_u32(smem);

    // Load Q/K hi-lo tiles (128 rows x 64 bf16 = 128 B/row), SW128 swizzle.
    {
        const uint4* sqh = (const uint4*)(g_qh + (size_t)(bh*SS + m0)*DH);
        const uint4* sql = (const uint4*)(g_ql + (size_t)(bh*SS + m0)*DH);
        const uint4* skh = (const uint4*)(g_kh + (size_t)(bh*SS + n0)*DH);
        const uint4* skl = (const uint4*)(g_kl + (size_t)(bh*SS + n0)*DH);
        for (int idx = tid; idx < 1024; idx += 256) {
            uint32_t off = (uint32_t)idx * 16;
            uint32_t sw = off ^ ((off >> 3) & 0x70);
            *(uint4*)(smem + OF_QH + sw) = sqh[idx];
            *(uint4*)(smem + OF_QL + sw) = sql[idx];
            *(uint4*)(smem + OF_KH + sw) = skh[idx];
            *(uint4*)(smem + OF_KL + sw) = skl[idx];
        }
    }
    __syncthreads();

    const int wid = tid >> 5, lane = tid & 31;
    const int wm = wid & 3, wn = wid >> 2;
    const int mw0 = wm * 32;        // warp row base within tile
    const int nw0 = wn * 64;        // warp col base within tile

    float acc[2][8][4];
#pragma unroll
    for (int i = 0; i < 2; i++)
#pragma unroll
        for (int j = 0; j < 8; j++)
#pragma unroll
            for (int q = 0; q < 4; q++) acc[i][j][q] = 0.f;

    const int lrow = lane & 15;         // ldmatrix row within 16
    const int lkh  = (lane >> 4) * 16;  // k-half byte offset

    const int aoffs[3] = { OF_QH, OF_QH, OF_QL };
    const int boffs[3] = { OF_KH, OF_KL, OF_KH };

#pragma unroll
    for (int s = 0; s < 3; s++) {
        const int aOff = aoffs[s], bOff = boffs[s];
#pragma unroll
        for (int ks = 0; ks < 4; ks++) {
            const uint32_t colb = (uint32_t)(ks*32 + lkh);
            uint32_t af[2][4];
#pragma unroll
            for (int mi = 0; mi < 2; mi++) {
                uint32_t off = (uint32_t)(mw0 + mi*16 + lrow) * 128 + colb;
                uint32_t sw = off ^ ((off >> 3) & 0x70);
                ldmx4(af[mi], sb + aOff + sw);
            }
            uint32_t bf[4][4];
#pragma unroll
            for (int nj = 0; nj < 4; nj++) {
                uint32_t off = (uint32_t)(nw0 + nj*16 + lrow) * 128 + colb;
                uint32_t sw = off ^ ((off >> 3) & 0x70);
                ldmx4(bf[nj], sb + bOff + sw);
            }
#pragma unroll
            for (int mi = 0; mi < 2; mi++)
#pragma unroll
                for (int nj = 0; nj < 4; nj++) {
                    mma16816(acc[mi][nj*2+0], af[mi], bf[nj][0], bf[nj][2]);
                    mma16816(acc[mi][nj*2+1], af[mi], bf[nj][1], bf[nj][3]);
                }
        }
    }

    // Epilogue: D[m][n] + res -> out. Frag: rows t>>2 (+8), cols (t&3)*2..+1.
    const float* R = res + (size_t)bh * SS * SS;
    float* O = out_scores + (size_t)bh * SS * SS;
#pragma unroll
    for (int mi = 0; mi < 2; mi++) {
#pragma unroll
        for (int half = 0; half < 2; half++) {
            int m = m0 + mw0 + mi*16 + (lane >> 2) + half*8;
            const float* rrow = R + (size_t)m * SS + n0 + nw0 + (lane & 3)*2;
            float* orow = O + (size_t)m * SS + n0 + nw0 + (lane & 3)*2;
#pragma unroll
            for (int nj = 0; nj < 8; nj++) {
                float2 r = *(const float2*)(rrow + nj*8);
                float2 o;
                o.x = acc[mi][nj][half*2+0] + r.x;
                o.y = acc[mi][nj][half*2+1] + r.y;
                *(float2*)(orow + nj*8) = o;
            }
        }
    }
}

// ---------------------------------------------------------------------------
// K3: per-row softmax stats over (scores + mask): rowmax m, sum l
// ---------------------------------------------------------------------------
__device__ __forceinline__ float warpRedMax(float v) {
#pragma unroll
    for (int o = 16; o > 0; o >>= 1) v = fmaxf(v, __shfl_xor_sync(0xffffffffu, v, o));
    return v;
}
__device__ __forceinline__ float warpRedSum(float v) {
#pragma unroll
    for (int o = 16; o > 0; o >>= 1) v += __shfl_xor_sync(0xffffffffu, v, o);
    return v;
}

__global__ __launch_bounds__(256) void softmax_stats_kernel(
    const float* __restrict__ scores, const float* __restrict__ mask)
{
    const int tid = threadIdx.x;
    __shared__ float red[8];

#pragma unroll
    for (int rr = 0; rr < 4; rr++) {
        const int row = blockIdx.x * 4 + rr;         // 0..49151
        const int b = row / (HH*SS);
        const float* sr = scores + (size_t)row * SS;
        const float* mr = mask + (size_t)b * SS;

        float vals[8];
        float lm = -CUDART_INF_F;
#pragma unroll
        for (int i = 0; i < 8; i++) {
            int c = tid + i*256;
            float v = sr[c] + mr[c];
            vals[i] = v;
            lm = fmaxf(lm, v);
        }

        float wm = warpRedMax(lm);
        if ((tid & 31) == 0) red[tid >> 5] = wm;
        __syncthreads();
        float bm = red[0];
#pragma unroll
        for (int w = 1; w < 8; w++) bm = fmaxf(bm, red[w]);

        float ls = 0.f;
#pragma unroll
        for (int i = 0; i < 8; i++) ls += __expf(vals[i] - bm);
        __syncthreads();
        float ws = warpRedSum(ls);
        if ((tid & 31) == 0) red[tid >> 5] = ws;
        __syncthreads();
        if (tid == 0) {
            float s = 0.f;
#pragma unroll
            for (int w = 0; w < 8; w++) s += red[w];
            g_m[row] = bm;
            g_l[row] = s;
        }
        __syncthreads();
    }
}

// ---------------------------------------------------------------------------
// K4: ctx = softmax(scores+mask) @ V, probs computed on the fly. (FFMA2 SIMT)
// ---------------------------------------------------------------------------
__global__ __launch_bounds__(256) void pv_kernel(
    const float* __restrict__ scores, const float* __restrict__ mask,
    float* __restrict__ ctx)
{
    const int bh = blockIdx.z;
    const int b = bh / HH, h = bh % HH;
    const float* P = scores + (size_t)bh * SS * SS;
    const float* V = g_v + (size_t)bh * SS * DH;
    const float* mr = mask + (size_t)b * SS;
    const int m0 = blockIdx.y * 128;
    const int tid = threadIdx.x;

    __shared__ __align__(16) float Ps[32][128+4];
    __shared__ __align__(16) float Vs[32][64+4];
    __shared__ float ms[128], rls[128];

    if (tid < 128) {
        int r = bh*SS + m0 + tid;
        ms[tid]  = g_m[r];
        rls[tid] = 1.0f / g_l[r];
    }
    __syncthreads();

    const int ty = tid >> 4;   // 0..15 -> 8 rows each
    const int tx = tid & 15;   // 0..15 -> 4 cols each
    const int pr  = tid >> 1;          // 0..127 (P tile row)
    const int pc0 = (tid & 1) * 16;    // 0 or 16

    u64 acc2[4][4];            // [i-pair][j]
#pragma unroll
    for (int i = 0; i < 4; i++)
#pragma unroll
        for (int j = 0; j < 4; j++) acc2[i][j] = 0ull;

    const float mrow = ms[pr];
    const float* prow = P + (size_t)(m0 + pr) * SS;

    for (int k0 = 0; k0 < SS; k0 += 32) {
#pragma unroll
        for (int i = 0; i < 4; i++) {
            int c = pc0 + i*4;
            float4 v = *(const float4*)(prow + k0 + c);
            float4 mk = *(const float4*)(mr + k0 + c);
            Ps[c+0][pr] = __expf(v.x + mk.x - mrow);
            Ps[c+1][pr] = __expf(v.y + mk.y - mrow);
            Ps[c+2][pr] = __expf(v.z + mk.z - mrow);
            Ps[c+3][pr] = __expf(v.w + mk.w - mrow);
        }
#pragma unroll
        for (int r = 0; r < 2; r++) {
            int vr = (tid >> 4) + r*16;
            int vc = (tid & 15) * 4;
            float4 v4 = *(const float4*)(V + (size_t)(k0+vr)*DH + vc);
            *(float4*)&Vs[vr][vc] = v4;
        }
        __syncthreads();
#pragma unroll
        for (int k = 0; k < 32; k++) {
            ulonglong2 a0 = *(const ulonglong2*)&Ps[k][ty*8];
            ulonglong2 a1 = *(const ulonglong2*)&Ps[k][ty*8+4];
            u64 ra2[4] = { a0.x, a0.y, a1.x, a1.y };
            float4 bv4 = *(const float4*)&Vs[k][tx*4];
            u64 rb2[4] = { dup2(bv4.x), dup2(bv4.y), dup2(bv4.z), dup2(bv4.w) };
#pragma unroll
            for (int i = 0; i < 4; i++)
#pragma unroll
                for (int j = 0; j < 4; j++)
                    fma2(acc2[i][j], ra2[i], rb2[j]);
        }
        __syncthreads();
    }

#pragma unroll
    for (int i2 = 0; i2 < 4; i2++) {
        float2 c0 = unpack2(acc2[i2][0]);
        float2 c1 = unpack2(acc2[i2][1]);
        float2 c2 = unpack2(acc2[i2][2]);
        float2 c3 = unpack2(acc2[i2][3]);

        int iA = 2*i2, iB = 2*i2 + 1;
        int mA = m0 + ty*8 + iA;
        int mB = m0 + ty*8 + iB;
        float rlA = rls[ty*8+iA];
        float rlB = rls[ty*8+iB];
        float4 oA = make_float4(c0.x*rlA, c1.x*rlA, c2.x*rlA, c3.x*rlA);
        float4 oB = make_float4(c0.y*rlB, c1.y*rlB, c2.y*rlB, c3.y*rlB);
        *(float4*)(ctx + ((size_t)b*SS + mA)*DD + h*DH + tx*4) = oA;
        *(float4*)(ctx + ((size_t)b*SS + mB)*DD + h*DH + tx*4) = oB;
    }
}

// ---------------------------------------------------------------------------
extern "C" void kernel_launch(void* const* d_in, const int* in_sizes, int n_in,
                              void* d_out, int out_size)
{
    const float* hid  = (const float*)d_in[0];
    const float* mask = (const float*)d_in[1];
    const float* res  = (const float*)d_in[2];
    const float* Wq = (const float*)d_in[3];
    const float* bq = (const float*)d_in[4];
    const float* Wk = (const float*)d_in[5];
    const float* bk = (const float*)d_in[6];
    const float* Wv = (const float*)d_in[7];
    const float* bv = (const float*)d_in[8];

    float* out_ctx    = (float*)d_out;
    float* out_scores = (float*)d_out + (size_t)BB*SS*DD;

    cudaFuncSetAttribute(scores_mma_kernel,
                         cudaFuncAttributeMaxDynamicSharedMemorySize, SMM_SMEM);

    qkv_kernel<<<dim3(DD/128, (BB*SS)/128, 3), 256>>>(hid, Wq, bq, Wk, bk, Wv, bv);
    scores_mma_kernel<<<dim3(SS/128, SS/128, BH), 256, SMM_SMEM>>>(res, out_scores);
    softmax_stats_kernel<<<dim3(ROWS_TOTAL/4), 256>>>(out_scores, mask);
    pv_kernel<<<dim3(1, SS/128, BH), 256>>>(out_scores, mask, out_ctx);
}